// round 15
// baseline (speedup 1.0000x reference)
#include <cuda_runtime.h>
#include <cstdint>

#define BATCH 64
#define SEQ   64
#define D     256
#define HALF  128
#define NCOL  640        // 5 * HALF (full gate width)
#define WCOL  320        // per-CTA gate columns (5 gates x 64)
#define WCOL_S 328       // smem stride for W rows (==8 mod 32: conflict-free frags)
#define DS    264        // smem stride for state rows (==8 mod 32)
#define F4R   66         // DS/4
#define MLPD  1024
#define KC    16         // k rows staged per chunk
#define NCHUNK (D / KC)  // 16
#define NTHREADS 512
#define NWARPS 16

typedef unsigned long long ull;

// ---------------- smem layout (floats) ----------------
static constexpr int SA_OFF    = 0;                          // 65*264 state buf A
static constexpr int SB_OFF    = SA_OFF + 65 * DS;           // 65*264 state buf B
static constexpr int SW_OFF    = SB_OFF + 65 * DS;           // 3*16*328 W ring (also MLP scratch)
static constexpr int SBIAS_OFF = SW_OFF + 3 * KC * WCOL_S;   // 640
static constexpr int SSELW_OFF = SBIAS_OFF + NCOL;           // 256
static constexpr int SLOG_OFF  = SSELW_OFF + D;              // 64
static constexpr int SPROB_OFF = SLOG_OFF + 64;              // 64
static constexpr int SCL_OFF   = SPROB_OFF + 64;             // 64
static constexpr int SCR_OFF   = SCL_OFF + 64;               // 64
static constexpr int SMEM_FLOATS = SCR_OFF + 64;             // 51,216
static constexpr int SMEM_BYTES  = SMEM_FLOATS * 4;          // 204,864 B

// ---------------- helpers ----------------
__device__ __forceinline__ unsigned smaddr(const void* p) {
    return (unsigned)__cvta_generic_to_shared(p);
}
__device__ __forceinline__ void cp16(unsigned dst, const void* src) {
    asm volatile("cp.async.ca.shared.global [%0], [%1], 16;\n" :: "r"(dst), "l"(src));
}
__device__ __forceinline__ void cp_commit() {
    asm volatile("cp.async.commit_group;\n" ::: "memory");
}
// m16n8k8 tf32 MMA: D += A*B  (A row-major 16x8, B col-major 8x8, fp32 accum)
__device__ __forceinline__ void mma_tf32(float* d, const unsigned* a, unsigned b0, unsigned b1) {
    asm volatile(
        "mma.sync.aligned.m16n8k8.row.col.f32.tf32.tf32.f32 "
        "{%0,%1,%2,%3}, {%4,%5,%6,%7}, {%8,%9}, {%0,%1,%2,%3};"
        : "+f"(d[0]), "+f"(d[1]), "+f"(d[2]), "+f"(d[3])
        : "r"(a[0]), "r"(a[1]), "r"(a[2]), "r"(a[3]), "r"(b0), "r"(b1));
}
// round-to-nearest tf32 (high part of the 3xTF32 split)
__device__ __forceinline__ unsigned tf32_hi(float x) {
    unsigned r; asm("cvt.rna.tf32.f32 %0, %1;" : "=r"(r) : "f"(x)); return r;
}
__device__ __forceinline__ float sigm(float x) {
    return __fdividef(1.f, 1.f + __expf(-x));
}
__device__ __forceinline__ float tanh_f(float x) {
    return 1.f - 2.f * __fdividef(1.f, __expf(2.f * x) + 1.f);
}
__device__ __forceinline__ float incl_scan(float v, int lane) {
    #pragma unroll
    for (int d = 1; d < 32; d <<= 1) {
        float n = __shfl_up_sync(0xffffffffu, v, d);
        if (lane >= d) v += n;
    }
    return v;
}
__device__ __forceinline__ unsigned ctarank() {
    unsigned r; asm("mov.u32 %0, %%cluster_ctarank;" : "=r"(r)); return r;
}
__device__ __forceinline__ void cl_arrive() {
    asm volatile("barrier.cluster.arrive.aligned;" ::: "memory");
}
__device__ __forceinline__ void cl_wait() {
    asm volatile("barrier.cluster.wait.aligned;" ::: "memory");
}
__device__ __forceinline__ void st_peer64(const float* p, unsigned peer, float hx, float hy) {
    unsigned la = smaddr(p), ra;
    asm("mapa.shared::cluster.u32 %0, %1, %2;" : "=r"(ra) : "r"(la), "r"(peer));
    ull pv; asm("mov.b64 %0, {%1, %2};" : "=l"(pv) : "f"(hx), "f"(hy));
    asm volatile("st.shared::cluster.b64 [%0], %1;" :: "r"(ra), "l"(pv) : "memory");
}
__device__ __forceinline__ void st_peer32(const float* p, unsigned peer, float v) {
    unsigned la = smaddr(p), ra;
    asm("mapa.shared::cluster.u32 %0, %1, %2;" : "=r"(ra) : "r"(la), "r"(peer));
    asm volatile("st.shared::cluster.b32 [%0], %1;" :: "r"(ra), "f"(v) : "memory");
}

// ---------------- kernel ----------------
__global__ __launch_bounds__(NTHREADS, 1) __cluster_dims__(2, 1, 1)
void pyramid_kernel(const int* __restrict__ sentences,   // int32 tokens (int64 probed)
                    const float* __restrict__ emb,
                    const float* __restrict__ comp_W,
                    const float* __restrict__ comp_b,
                    const float* __restrict__ sel_w,
                    const float* __restrict__ sel_b,
                    const float* __restrict__ w0, const float* __restrict__ b0,
                    const float* __restrict__ w1, const float* __restrict__ b1,
                    const float* __restrict__ cw, const float* __restrict__ cb,
                    float* __restrict__ out)
{
    extern __shared__ float sm[];
    float* sBufA = sm + SA_OFF;
    float* sBufB = sm + SB_OFF;
    float* sW    = sm + SW_OFF;
    float* sbias = sm + SBIAS_OFF;
    float* sselw = sm + SSELW_OFF;
    float* slog  = sm + SLOG_OFF;
    float* sprob = sm + SPROB_OFF;
    float* scl   = sm + SCL_OFF;
    float* scr   = sm + SCR_OFF;

    const int tid  = threadIdx.x;
    const int lane = tid & 31;
    const int wid  = tid >> 5;
    const unsigned rank = ctarank();
    const unsigned peer = rank ^ 1u;
    const int b = blockIdx.x >> 1;      // cluster id = batch element

    // dtype probe (JAX x64-disabled gives int32; see R7 analysis)
    const bool is64 = (sentences[1] == 0 && sentences[3] == 0 &&
                       sentences[5] == 0 && sentences[7] == 0);

    // ---- init: gather embeddings into sBufA (replicated in both CTAs) ----
    {
        float4* a4 = (float4*)sBufA;
        const float4* e4 = (const float4*)emb;
        for (int i = tid; i < SEQ * (D / 4); i += NTHREADS) {
            int row = i >> 6;
            int c4  = i & 63;
            int idx = b * SEQ + row;
            int tok = is64 ? sentences[idx * 2] : sentences[idx];
            a4[row * F4R + c4] = e4[tok * 64 + c4];
        }
        float4 z4 = make_float4(0.f, 0.f, 0.f, 0.f);
        for (int i = 64 * F4R + tid; i < 65 * F4R; i += NTHREADS) a4[i] = z4;  // zero row 64
        for (int i = tid; i < NCOL; i += NTHREADS) sbias[i] = comp_b[i];
        for (int i = tid; i < D;    i += NTHREADS) sselw[i] = sel_w[i];
    }
    const float selb = sel_b[0];
    __syncthreads();

    float* sCur = sBufA;
    float* sNxt = sBufB;

    // warp tiling: mgrp picks positions [32*mgrp, +32); cwin picks hidden cols [8*cwin, +8)
    const int mgrp = wid >> 3;
    const int cwin = wid & 7;
    const int l4   = lane >> 2;   // 0..7
    const int la   = lane & 3;    // 0..3
    const int m0g  = (int)rank * 64 + cwin * 8 + 2 * la;   // global hidden pair base

    // stage chunk c of our 320 W columns into ring buffer c%3 (stride WCOL_S)
    auto stage = [&](int c) {
        unsigned dstb = smaddr(sW + (c % 3) * KC * WCOL_S);
        const float* src = comp_W + c * KC * NCOL + (int)rank * 64;
        #pragma unroll
        for (int i = tid; i < KC * WCOL / 4; i += NTHREADS) {   // 1280 cp16s
            int kk  = i / 80;
            int rem = i - kk * 80;
            int g   = rem >> 4;
            int q   = rem & 15;
            cp16(dstb + (unsigned)((kk * WCOL_S + g * 64 + q * 4) * 4),
                 src + kk * NCOL + g * HALF + q * 4);
        }
        cp_commit();
    };

    stage(0);
    stage(1);
    cl_arrive();    // A2 (first-layer peer-write guard pairs with W2 below)

    for (int P = SEQ - 1; P >= 1; --P) {
        const bool activeW = (32 * mgrp < P);

        // ====== GEMM via 3xTF32 tensor cores: C[64,320] = X[64,256] @ W ======
        float acc[5][2][4];   // gate, m16-tile, frag
        if (activeW) {
            #pragma unroll
            for (int g = 0; g < 5; ++g)
                #pragma unroll
                for (int mt = 0; mt < 2; ++mt)
                    #pragma unroll
                    for (int f = 0; f < 4; ++f) acc[g][mt][f] = 0.f;
        }

        for (int c = 0; c < NCHUNK; ++c) {
            if (c == NCHUNK - 1)
                asm volatile("cp.async.wait_group 0;\n" ::: "memory");
            else
                asm volatile("cp.async.wait_group 1;\n" ::: "memory");
            __syncthreads();                 // chunk c visible; chunk c-1 fully consumed
            if (c + 2 < NCHUNK) stage(c + 2);

            if (activeW) {
                const float* wbase = sW + (c % 3) * KC * WCOL_S + cwin * 8 + l4;
                #pragma unroll
                for (int ks = 0; ks < KC; ks += 8) {
                    const int gk = c * KC + ks;
                    // k < 128 -> h of states[p]; k >= 128 -> h of states[p+1]
                    const float* arow = sCur + (gk >= HALF ? DS : 0) + (gk & (HALF - 1)) + la
                                        + (mgrp * 32 + l4) * DS;
                    unsigned ahi[2][4], alo[2][4];
                    #pragma unroll
                    for (int mt = 0; mt < 2; ++mt) {
                        const float* ap = arow + mt * 16 * DS;
                        float v0 = ap[0];
                        float v1 = ap[8 * DS];
                        float v2 = ap[4];
                        float v3 = ap[8 * DS + 4];
                        ahi[mt][0] = tf32_hi(v0); alo[mt][0] = __float_as_uint(v0 - __uint_as_float(ahi[mt][0]));
                        ahi[mt][1] = tf32_hi(v1); alo[mt][1] = __float_as_uint(v1 - __uint_as_float(ahi[mt][1]));
                        ahi[mt][2] = tf32_hi(v2); alo[mt][2] = __float_as_uint(v2 - __uint_as_float(ahi[mt][2]));
                        ahi[mt][3] = tf32_hi(v3); alo[mt][3] = __float_as_uint(v3 - __uint_as_float(ahi[mt][3]));
                    }
                    const float* bp = wbase + (ks + la) * WCOL_S;
                    #pragma unroll
                    for (int g = 0; g < 5; ++g) {
                        float bf0 = bp[g * 64];
                        float bf1 = bp[4 * WCOL_S + g * 64];
                        unsigned bh0 = tf32_hi(bf0);
                        unsigned bh1 = tf32_hi(bf1);
                        unsigned bl0 = __float_as_uint(bf0 - __uint_as_float(bh0));
                        unsigned bl1 = __float_as_uint(bf1 - __uint_as_float(bh1));
                        // Ahi*Bhi + Ahi*Blo + Alo*Bhi  (3xTF32 ~ fp32 accuracy)
                        mma_tf32(acc[g][0], ahi[0], bh0, bh1);
                        mma_tf32(acc[g][1], ahi[1], bh0, bh1);
                        mma_tf32(acc[g][0], ahi[0], bl0, bl1);
                        mma_tf32(acc[g][1], ahi[1], bl0, bl1);
                        mma_tf32(acc[g][0], alo[0], bh0, bh1);
                        mma_tf32(acc[g][1], alo[1], bh0, bh1);
                    }
                }
            }
        }

        cl_wait();   // W2: peer finished its previous-layer update -> safe to write its sNxt

        // ======== gates (registers) + local & peer state writes ========
        if (activeW) {
            #pragma unroll
            for (int mt = 0; mt < 2; ++mt)
            #pragma unroll
            for (int hf = 0; hf < 2; ++hf) {
                const int p = mgrp * 32 + mt * 16 + hf * 8 + l4;
                if (p < P) {
                    float ivx = acc[0][mt][2*hf], ivy = acc[0][mt][2*hf+1];
                    float flx = acc[1][mt][2*hf], fly = acc[1][mt][2*hf+1];
                    float frx = acc[2][mt][2*hf], fry = acc[2][mt][2*hf+1];
                    float ggx = acc[3][mt][2*hf], ggy = acc[3][mt][2*hf+1];
                    float oox = acc[4][mt][2*hf], ooy = acc[4][mt][2*hf+1];
                    float2 cl = *(const float2*)(sCur + p * DS + HALF + m0g);
                    float2 cr = *(const float2*)(sCur + (p + 1) * DS + HALF + m0g);

                    float cx = sigm(flx + sbias[1 * HALF + m0g])     * cl.x
                             + sigm(frx + sbias[2 * HALF + m0g])     * cr.x
                             + sigm(ivx + sbias[0 * HALF + m0g])     * tanh_f(ggx + sbias[3 * HALF + m0g]);
                    float cy = sigm(fly + sbias[1 * HALF + m0g + 1]) * cl.y
                             + sigm(fry + sbias[2 * HALF + m0g + 1]) * cr.y
                             + sigm(ivy + sbias[0 * HALF + m0g + 1]) * tanh_f(ggy + sbias[3 * HALF + m0g + 1]);
                    float hx = sigm(oox + sbias[4 * HALF + m0g])     * tanh_f(cx);
                    float hy = sigm(ooy + sbias[4 * HALF + m0g + 1]) * tanh_f(cy);

                    float* ph = sNxt + p * DS + m0g;
                    float* pc = sNxt + p * DS + HALF + m0g;
                    *(float2*)ph = make_float2(hx, hy);
                    *(float2*)pc = make_float2(cx, cy);
                    st_peer64(ph, peer, hx, hy);
                    st_peer64(pc, peer, cx, cy);
                }
            }
        }
        cl_arrive(); cl_wait();   // sync1: peer's state half visible in sNxt

        // early-stage next layer's W chunks 0,1 (W layer-invariant; buffers free)
        if (P > 1) { stage(0); stage(1); }

        // ================= logits: comp @ sel_w (full, local) =================
        for (int p = wid; p < P; p += NWARPS) {
            const float* cp = sNxt + p * DS;
            float s = 0.f;
            #pragma unroll
            for (int r = 0; r < 2; ++r) {
                float4 v = *(const float4*)(cp + lane * 8 + r * 4);
                float4 w = *(const float4*)(sselw + lane * 8 + r * 4);
                s += v.x * w.x + v.y * w.y + v.z * w.z + v.w * w.w;
            }
            #pragma unroll
            for (int d2 = 16; d2; d2 >>= 1) s += __shfl_xor_sync(0xffffffffu, s, d2);
            if (lane == 0) slog[p] = s + selb;
        }
        __syncthreads();

        // ================= softmax + exclusive scans (warp 0) =================
        if (wid == 0) {
            float v0 = (lane      < P) ? slog[lane]      : -3.4e38f;
            float v1 = (lane + 32 < P) ? slog[lane + 32] : -3.4e38f;
            float mx = fmaxf(v0, v1);
            #pragma unroll
            for (int d2 = 16; d2; d2 >>= 1) mx = fmaxf(mx, __shfl_xor_sync(0xffffffffu, mx, d2));
            float e0 = (lane      < P) ? __expf(v0 - mx) : 0.f;
            float e1 = (lane + 32 < P) ? __expf(v1 - mx) : 0.f;
            float ss = e0 + e1;
            #pragma unroll
            for (int d2 = 16; d2; d2 >>= 1) ss += __shfl_xor_sync(0xffffffffu, ss, d2);
            float inv = __fdividef(1.f, ss);
            float p0 = e0 * inv, p1 = e1 * inv;
            float s0 = incl_scan(p0, lane);
            float t0 = __shfl_sync(0xffffffffu, s0, 31);
            float s1 = incl_scan(p1, lane) + t0;
            float tt = __shfl_sync(0xffffffffu, s1, 31);
            if (lane < P)      { sprob[lane]      = p0; scr[lane]      = s0 - p0; scl[lane]      = tt - s0; }
            if (lane + 32 < P) { sprob[lane + 32] = p1; scr[lane + 32] = s1 - p1; scl[lane + 32] = tt - s1; }
        }
        __syncthreads();

        // ================= state update (in-place into comp buffer) =================
        {
            float4*       nx4 = (float4*)sNxt;
            const float4* cu4 = (const float4*)sCur;
            for (int i = tid; i < P * 64; i += NTHREADS) {
                int   p  = i >> 6;
                int   cc = i & 63;
                int   idx = p * F4R + cc;
                float a  = scl[p], r = scr[p], q = sprob[p];
                float4 L = cu4[idx];
                float4 R = cu4[idx + F4R];
                float4 C = nx4[idx];
                float4 o;
                o.x = a * L.x + r * R.x + q * C.x;
                o.y = a * L.y + r * R.y + q * C.y;
                o.z = a * L.z + r * R.z + q * C.z;
                o.w = a * L.w + r * R.w + q * C.w;
                nx4[idx] = o;
            }
            // zero ALL rows >= P (GEMM reads every row 0..64 next layer)
            float4 z4 = make_float4(0.f, 0.f, 0.f, 0.f);
            for (int i = P * F4R + tid; i < 65 * F4R; i += NTHREADS) nx4[i] = z4;
        }
        cl_arrive();       // A2: our update done; peer may write our (old) sCur next layer
        __syncthreads();   // local: update visible before next GEMM reads it

        float* t2 = sCur; sCur = sNxt; sNxt = t2;
    }

    cl_wait();   // pair final A2; peer finished last update

    // ================= MLP head: split 512 cols per CTA, DSMEM exchange =================
    {
        float* sZ1 = sW;            // 1024 scratch
        float* sZ2 = sW + MLPD;     // 1024 scratch
        const float* h = sCur;      // 256 (replicated; row 0 contiguous)
        {
            const int c = (int)rank * 512 + tid;
            float a = 0.f;
            #pragma unroll 4
            for (int k = 0; k < D; ++k) a += h[k] * w0[k * MLPD + c];
            a = fmaxf(a + b0[c], 0.f);
            sZ1[c] = a;
            st_peer32(&sZ1[c], peer, a);
        }
        cl_arrive(); cl_wait();
        {
            const int c = (int)rank * 512 + tid;
            float a = 0.f;
            #pragma unroll 4
            for (int k = 0; k < MLPD; ++k) a += sZ1[k] * w1[k * MLPD + c];
            a = fmaxf(a + b1[c], 0.f);
            sZ2[c] = a;
            st_peer32(&sZ2[c], peer, a);
        }
        cl_arrive(); cl_wait();
        if (rank == 0 && wid == 0) {
            #pragma unroll
            for (int c = 0; c < 3; ++c) {
                float s = 0.f;
                for (int k = lane; k < MLPD; k += 32) s += sZ2[k] * cw[k * 3 + c];
                #pragma unroll
                for (int d2 = 16; d2; d2 >>= 1) s += __shfl_xor_sync(0xffffffffu, s, d2);
                if (lane == 0) out[b * 3 + c] = s + cb[c];
            }
        }
    }
}

// ---------------- launch ----------------
extern "C" void kernel_launch(void* const* d_in, const int* in_sizes, int n_in,
                              void* d_out, int out_size)
{
    (void)in_sizes; (void)n_in; (void)out_size;
    const int* sentences = (const int*)d_in[0];
    // d_in[1] = transitions (unused)
    const float* emb    = (const float*)d_in[2];
    const float* comp_W = (const float*)d_in[3];
    const float* comp_b = (const float*)d_in[4];
    const float* sel_w  = (const float*)d_in[5];
    const float* sel_b  = (const float*)d_in[6];
    const float* w0     = (const float*)d_in[7];
    const float* b0     = (const float*)d_in[8];
    const float* w1     = (const float*)d_in[9];
    const float* b1     = (const float*)d_in[10];
    const float* cw     = (const float*)d_in[11];
    const float* cb     = (const float*)d_in[12];
    float* out = (float*)d_out;

    cudaFuncSetAttribute(pyramid_kernel,
                         cudaFuncAttributeMaxDynamicSharedMemorySize, SMEM_BYTES);
    pyramid_kernel<<<BATCH * 2, NTHREADS, SMEM_BYTES>>>(
        sentences, emb, comp_W, comp_b, sel_w, sel_b,
        w0, b0, w1, b1, cw, cb, out);
}